// round 13
// baseline (speedup 1.0000x reference)
#include <cuda_runtime.h>
#include <cuda_fp16.h>
#include <cstdint>
#include <cstddef>

#define NROWS 4096
#define ODIM  512
#define IDIM  512
#define DDIM  64

#define BM 128
#define BN 64
#define NTH 256
#define NT_W 256            // W tiles (2 i each); tile 256 = bias
#define NSUP 128            // super-tiles of 2 W tiles

#define BPITCHB 272u                       // 68 words ≡ 4 mod 32 -> ldmatrix 8-row conflict-free
#define B_STAGE (64u * BPITCHB)            // 17408 B
#define NSTAGE 6
#define SMEM_TOTAL (int)(6u * B_STAGE)     // 104448 B -> 2 CTAs/SM

__device__ float  g_xT[IDIM * NROWS];                  // x transposed: [512][4096] fp32
__device__ __half g_Wt[(size_t)IDIM * ODIM * DDIM];    // W re-laid: [i][o][d] fp16
__device__ __half g_bt[ODIM * DDIM];                   // b1 re-laid: [o][d] fp16

// ---------------- helpers ----------------
__device__ __forceinline__ uint32_t smem_u32(const void* p) {
    uint32_t a;
    asm("{ .reg .u64 t; cvta.to.shared.u64 t, %1; cvt.u32.u64 %0, t; }" : "=r"(a) : "l"(p));
    return a;
}
__device__ __forceinline__ uint32_t f2h2(float f) {   // (h,h) packed fp16x2
    uint32_t r;
    asm("{ .reg .b16 h; cvt.rn.f16.f32 h, %1; mov.b32 %0, {h, h}; }" : "=r"(r) : "f"(f));
    return r;
}
__device__ __forceinline__ uint32_t pack2(float lo, float hi) {
    __half2 h = __floats2half2_rn(lo, hi);
    return *reinterpret_cast<uint32_t*>(&h);
}
#define CP_ASYNC16(dst, src) \
    asm volatile("cp.async.cg.shared.global [%0], [%1], 16;" :: "r"(dst), "l"(src) : "memory")
#define CP_COMMIT() asm volatile("cp.async.commit_group;" ::: "memory")
#define CP_WAIT2()  asm volatile("cp.async.wait_group 2;" ::: "memory")

#define LDMX4(r0, r1, r2, r3, a) \
    asm volatile("ldmatrix.sync.aligned.m8n8.x4.shared.b16 {%0,%1,%2,%3}, [%4];" \
        : "=r"(r0), "=r"(r1), "=r"(r2), "=r"(r3) : "r"(a))
#define HMUL2(d, a, b) asm("mul.rn.f16x2 %0, %1, %2;" : "=r"(d) : "r"(a), "r"(b))
#define REDADD(addr, val) \
    asm volatile("red.global.add.f32 [%0], %1;" :: "l"(addr), "f"(val) : "memory")

__device__ __forceinline__ void mma_f16_16816(float& c0, float& c1, float& c2, float& c3,
                                              uint32_t a0, uint32_t a1, uint32_t a2, uint32_t a3,
                                              uint32_t b0, uint32_t b1) {
    asm volatile(
        "mma.sync.aligned.m16n8k16.row.col.f32.f16.f16.f32 "
        "{%0,%1,%2,%3}, {%4,%5,%6,%7}, {%8,%9}, {%0,%1,%2,%3};"
        : "+f"(c0), "+f"(c1), "+f"(c2), "+f"(c3)
        : "r"(a0), "r"(a1), "r"(a2), "r"(a3), "r"(b0), "r"(b1));
}

// ---------------- prepass kernels ----------------
__global__ void __launch_bounds__(1024) transpose_x(const float* __restrict__ x) {
    __shared__ float t[32][33];
    const int bi = blockIdx.x * 32;
    const int bn = blockIdx.y * 32;
    t[threadIdx.y][threadIdx.x] = x[(size_t)(bn + threadIdx.y) * IDIM + bi + threadIdx.x];
    __syncthreads();
    g_xT[(size_t)(bi + threadIdx.y) * NROWS + bn + threadIdx.x] = t[threadIdx.x][threadIdx.y];
}

// W[d][i][o] fp32 -> g_Wt[i][o][d] fp16
__global__ void __launch_bounds__(1024) prep_w(const float* __restrict__ W) {
    __shared__ float sm[32][65];
    const int i  = blockIdx.x;
    const int ob = blockIdx.y * 32;
    const int tx = threadIdx.x, ty = threadIdx.y;
#pragma unroll
    for (int k = 0; k < 2; ++k) {
        int d = ty + k * 32;
        sm[tx][d] = W[(size_t)d * IDIM * ODIM + (size_t)i * ODIM + ob + tx];
    }
    __syncthreads();
    __half2 h = __floats2half2_rn(sm[ty][2 * tx], sm[ty][2 * tx + 1]);
    reinterpret_cast<__half2*>(g_Wt)[((size_t)i * ODIM + ob + ty) * 32 + tx] = h;
}

// b1[d][o] fp32 -> g_bt[o][d] fp16
__global__ void __launch_bounds__(1024) prep_b(const float* __restrict__ b1) {
    __shared__ float sm[32][65];
    const int ob = blockIdx.x * 32;
    const int tx = threadIdx.x, ty = threadIdx.y;
#pragma unroll
    for (int k = 0; k < 2; ++k) {
        int d = ty + k * 32;
        sm[tx][d] = b1[(size_t)d * ODIM + ob + tx];
    }
    __syncthreads();
    __half2 h = __floats2half2_rn(sm[ty][2 * tx], sm[ty][2 * tx + 1]);
    reinterpret_cast<__half2*>(g_bt)[(size_t)(ob + ty) * 32 + tx] = h;
}

// ---------------- main kernel: 32x64 warps, d-split halves, partial-C reduce ----------------
__global__ void __launch_bounds__(NTH, 2) mlp_mma(
    const float* __restrict__ var,
    float* __restrict__ out)
{
    extern __shared__ __align__(128) uint8_t smem[];
    const uint32_t s0 = smem_u32(smem);

    const int tid  = threadIdx.x;
    const int lane = tid & 31;
    const int w    = tid >> 5;
    const int rowBase = blockIdx.y * BM;
    const int colBase = blockIdx.x * BN;

    const int wmb = (w & 3) * 32;   // 32-row m-band (4 bands)
    const int kg  = w >> 2;         // d-half: 0 -> d 0..31, 1 -> d 32..63
    const int G   = 2 * kg;         // base d-group
    const int c   = lane & 3;
    const int g   = lane >> 2;

    // ----- this thread's 4 fragment rows -----
    int xr[4];
#pragma unroll
    for (int rr = 0; rr < 4; ++rr)
        xr[rr] = rowBase + wmb + (rr >> 1) * 16 + (rr & 1) * 8 + g;

    // ----- vh[rr][lg][h]: fp16x2 for d = (G+lg)*16 + h*8 + {2c,2c+1} (16 regs) -----
    uint32_t vh[4][2][2];
#pragma unroll
    for (int rr = 0; rr < 4; ++rr) {
        const float* vp = var + (size_t)xr[rr] * DDIM;
#pragma unroll
        for (int lg = 0; lg < 2; ++lg) {
            float2 p0 = *reinterpret_cast<const float2*>(vp + (G + lg) * 16 + 2 * c);
            float2 p1 = *reinterpret_cast<const float2*>(vp + (G + lg) * 16 + 8 + 2 * c);
            vh[rr][lg][0] = pack2(p0.x, p0.y);
            vh[rr][lg][1] = pack2(p1.x, p1.y);
        }
    }

    // ----- ldmatrix per-lane base (warp spans all 64 o-rows) -----
    const int q = lane >> 3, r8 = lane & 7;
    const uint32_t bRowLd = (uint32_t)(((q >> 1) << 3) + r8) * BPITCHB + (uint32_t)(q & 1) * 16u;

    // ----- B loader (cp.async) -----
    const int bo = tid >> 2;
    const int ci = tid & 3;
    auto issueB = [&](int t) {
        if (t <= NT_W) {
            const uint32_t dstBase = s0 + (uint32_t)(t % NSTAGE) * B_STAGE + (uint32_t)bo * BPITCHB;
            if (t < NT_W) {
                const __half* p0 = g_Wt + ((size_t)(2 * t) * ODIM + colBase + bo) * DDIM;
                const __half* p1 = p0 + (size_t)ODIM * DDIM;
#pragma unroll
                for (int cc = 0; cc < 2; ++cc) {
                    uint32_t ch = (uint32_t)(ci + cc * 4);
                    CP_ASYNC16(dstBase + ch * 16u,        p0 + ch * 8);
                    CP_ASYNC16(dstBase + 128u + ch * 16u, p1 + ch * 8);
                }
            } else {
                const __half* p0 = g_bt + (size_t)(colBase + bo) * DDIM;
#pragma unroll
                for (int cc = 0; cc < 2; ++cc) {
                    uint32_t ch = (uint32_t)(ci + cc * 4);
                    CP_ASYNC16(dstBase + ch * 16u, p0 + ch * 8);
                }
            }
        }
        CP_COMMIT();
    };
    auto loadXh = [&](int t, uint32_t (&dst)[2][4]) {
        if (t < NT_W) {
#pragma unroll
            for (int il = 0; il < 2; ++il)
#pragma unroll
                for (int rr = 0; rr < 4; ++rr)
                    dst[il][rr] = f2h2(__ldg(&g_xT[(size_t)(2 * t + il) * NROWS + xr[rr]]));
        }
    };

    float C[2][8][4];
#pragma unroll
    for (int mt = 0; mt < 2; ++mt)
#pragma unroll
        for (int nt = 0; nt < 8; ++nt)
#pragma unroll
            for (int qq = 0; qq < 4; ++qq) C[mt][nt][qq] = 0.0f;

    // ks per step: (lg, il): (0,0)(1,0)(0,1)(1,1) -> ks = il*4 + G + lg
    const int ksT[4] = {G, G + 1, G + 4, G + 5};

    // ----- prologue -----
    issueB(0); issueB(1); issueB(2); issueB(3);
    uint32_t xhc[2][4], xhn[2][4];
    loadXh(0, xhc);

    // ----- mainloop: 128 super-tiles -----
    for (int j = 0; j < NSUP; ++j) {
        CP_WAIT2();
        __syncthreads();
        issueB(2 * j + 4);
        issueB(2 * j + 5);

#pragma unroll
        for (int tt = 0; tt < 2; ++tt) {
            const int t = 2 * j + tt;
            loadXh(t + 1, xhn);
            const uint32_t base = s0 + (uint32_t)(t % NSTAGE) * B_STAGE + bRowLd;

            uint32_t bb[2][8], a[2][4];
            // prefetch half-step 0: step 0 (ks=ksT[0]), nt 0..3
            LDMX4(bb[0][0], bb[0][1], bb[0][2], bb[0][3], base + (uint32_t)ksT[0] * 32u);
            LDMX4(bb[0][4], bb[0][5], bb[0][6], bb[0][7],
                  base + (uint32_t)ksT[0] * 32u + 16u * BPITCHB);

#pragma unroll
            for (int hs = 0; hs < 8; ++hs) {
                const int step = hs >> 1, halfn = hs & 1;
                const int lg = step & 1, il = step >> 1;
                const int cur = hs & 1;   // buffer parity
                if (hs < 7) {
                    const int ns = (hs + 1) >> 1, nh = (hs + 1) & 1;
                    const uint32_t nb = base + (uint32_t)ksT[ns] * 32u
                                      + (uint32_t)nh * (32u * BPITCHB);
                    const int nxt = cur ^ 1;
                    LDMX4(bb[nxt][0], bb[nxt][1], bb[nxt][2], bb[nxt][3], nb);
                    LDMX4(bb[nxt][4], bb[nxt][5], bb[nxt][6], bb[nxt][7],
                          nb + 16u * BPITCHB);
                }
                if (halfn == 0) {   // a shared by both half-steps of this step
#pragma unroll
                    for (int mt = 0; mt < 2; ++mt) {
                        HMUL2(a[mt][0], xhc[il][mt * 2 + 0], vh[mt * 2 + 0][lg][0]);
                        HMUL2(a[mt][1], xhc[il][mt * 2 + 1], vh[mt * 2 + 1][lg][0]);
                        HMUL2(a[mt][2], xhc[il][mt * 2 + 0], vh[mt * 2 + 0][lg][1]);
                        HMUL2(a[mt][3], xhc[il][mt * 2 + 1], vh[mt * 2 + 1][lg][1]);
                    }
                }
#pragma unroll
                for (int mt = 0; mt < 2; ++mt)
#pragma unroll
                    for (int j2 = 0; j2 < 4; ++j2) {
                        const int nt = halfn * 4 + j2;
                        mma_f16_16816(C[mt][nt][0], C[mt][nt][1], C[mt][nt][2], C[mt][nt][3],
                                      a[mt][0], a[mt][1], a[mt][2], a[mt][3],
                                      bb[cur][2 * j2], bb[cur][2 * j2 + 1]);
                    }
            }
#pragma unroll
            for (int il = 0; il < 2; ++il)
#pragma unroll
                for (int rr = 0; rr < 4; ++rr) xhc[il][rr] = xhn[il][rr];
        }
    }

    // ----- bias tile (t=256, stage 4): each kg does its two lg steps (il = 0 slots, x = 1) -----
    {
        CP_WAIT2();
        __syncthreads();
        const uint32_t base = s0 + (uint32_t)(NT_W % NSTAGE) * B_STAGE + bRowLd;
#pragma unroll
        for (int lg = 0; lg < 2; ++lg) {
            const int ks = G + lg;    // bias valid for ks 0..3: kg0 -> {0,1}, kg1 -> {2,3}
#pragma unroll
            for (int halfn = 0; halfn < 2; ++halfn) {
                uint32_t b[8];
                const uint32_t nb = base + (uint32_t)ks * 32u + (uint32_t)halfn * (32u * BPITCHB);
                LDMX4(b[0], b[1], b[2], b[3], nb);
                LDMX4(b[4], b[5], b[6], b[7], nb + 16u * BPITCHB);
                uint32_t a[2][4];
#pragma unroll
                for (int mt = 0; mt < 2; ++mt) {   // x = 1 -> a = v exactly
                    a[mt][0] = vh[mt * 2 + 0][lg][0];
                    a[mt][1] = vh[mt * 2 + 1][lg][0];
                    a[mt][2] = vh[mt * 2 + 0][lg][1];
                    a[mt][3] = vh[mt * 2 + 1][lg][1];
                }
#pragma unroll
                for (int mt = 0; mt < 2; ++mt)
#pragma unroll
                    for (int j2 = 0; j2 < 4; ++j2) {
                        const int nt = halfn * 4 + j2;
                        mma_f16_16816(C[mt][nt][0], C[mt][nt][1], C[mt][nt][2], C[mt][nt][3],
                                      a[mt][0], a[mt][1], a[mt][2], a[mt][3],
                                      b[2 * j2], b[2 * j2 + 1]);
                    }
            }
        }
    }

    // ----- epilogue: kg0 stores its partial; kg1 atomically adds its partial -----
    if (kg == 0) {
#pragma unroll
        for (int mt = 0; mt < 2; ++mt) {
            const int r0 = rowBase + wmb + mt * 16 + g;
#pragma unroll
            for (int nt = 0; nt < 8; ++nt) {
                const int c0i = colBase + nt * 8 + c * 2;
                float2 v0, v1;
                v0.x = C[mt][nt][0]; v0.y = C[mt][nt][1];
                v1.x = C[mt][nt][2]; v1.y = C[mt][nt][3];
                *reinterpret_cast<float2*>(&out[(size_t)r0 * ODIM + c0i]) = v0;
                *reinterpret_cast<float2*>(&out[(size_t)(r0 + 8) * ODIM + c0i]) = v1;
            }
        }
    }
    __syncthreads();   // kg0's global stores visible before kg1's RED
    if (kg == 1) {
#pragma unroll
        for (int mt = 0; mt < 2; ++mt) {
            const int r0 = rowBase + wmb + mt * 16 + g;
#pragma unroll
            for (int nt = 0; nt < 8; ++nt) {
                const int c0i = colBase + nt * 8 + c * 2;
                float* p0 = &out[(size_t)r0 * ODIM + c0i];
                float* p1 = &out[(size_t)(r0 + 8) * ODIM + c0i];
                REDADD(p0,     C[mt][nt][0]);
                REDADD(p0 + 1, C[mt][nt][1]);
                REDADD(p1,     C[mt][nt][2]);
                REDADD(p1 + 1, C[mt][nt][3]);
            }
        }
    }
}

// ---------------- host ----------------
extern "C" void kernel_launch(void* const* d_in, const int* in_sizes, int n_in,
                              void* d_out, int out_size) {
    const float* x   = (const float*)d_in[0];   // [4096, 512]
    const float* var = (const float*)d_in[1];   // [4096, 64]
    const float* W   = (const float*)d_in[2];   // [64, 512, 512]
    const float* b1  = (const float*)d_in[3];   // [64, 512]
    float* out       = (float*)d_out;           // [4096, 512]

    {
        dim3 tb(32, 32), tg(IDIM / 32, NROWS / 32);
        transpose_x<<<tg, tb>>>(x);
    }
    {
        dim3 tb(32, 32), tg(IDIM, ODIM / 32);
        prep_w<<<tg, tb>>>(W);
    }
    {
        dim3 tb(32, 32);
        prep_b<<<ODIM / 32, tb>>>(b1);
    }

    cudaFuncSetAttribute(mlp_mma, cudaFuncAttributeMaxDynamicSharedMemorySize, SMEM_TOTAL);
    dim3 grid(ODIM / BN, NROWS / BM);   // (8, 32) = 256 CTAs, 2 per SM
    mlp_mma<<<grid, NTH, SMEM_TOTAL>>>(var, out);
}

// round 15
// speedup vs baseline: 1.0952x; 1.0952x over previous
#include <cuda_runtime.h>
#include <cuda_fp16.h>
#include <cstdint>
#include <cstddef>

#define NROWS 4096
#define ODIM  512
#define IDIM  512
#define DDIM  64

#define BM 128
#define BN 64
#define NTH 256
#define NT_W 256            // W tiles (2 i each); tile 256 = bias

#define BPITCHB 272u                       // 68 words ≡ 4 mod 32 -> ldmatrix 8-row conflict-free
#define B_STAGE (64u * BPITCHB)            // 17408 B
#define NSTAGE 6
#define BAR_OFF (6u * B_STAGE)             // 104448
#define SMEM_TOTAL (int)(BAR_OFF + 128)    // 104576 -> 2 CTAs/SM

__device__ float  g_xT[IDIM * NROWS];                  // x transposed: [512][4096] fp32
__device__ __half g_Wt[(size_t)IDIM * ODIM * DDIM];    // W re-laid: [i][o][d] fp16
__device__ __half g_bt[ODIM * DDIM];                   // b1 re-laid: [o][d] fp16

// ---------------- helpers ----------------
__device__ __forceinline__ uint32_t smem_u32(const void* p) {
    uint32_t a;
    asm("{ .reg .u64 t; cvta.to.shared.u64 t, %1; cvt.u32.u64 %0, t; }" : "=r"(a) : "l"(p));
    return a;
}
__device__ __forceinline__ uint32_t f2h2(float f) {   // (h,h) packed fp16x2
    uint32_t r;
    asm("{ .reg .b16 h; cvt.rn.f16.f32 h, %1; mov.b32 %0, {h, h}; }" : "=r"(r) : "f"(f));
    return r;
}
__device__ __forceinline__ uint32_t pack2(float lo, float hi) {
    __half2 h = __floats2half2_rn(lo, hi);
    return *reinterpret_cast<uint32_t*>(&h);
}
#define CP_ASYNC16(dst, src) \
    asm volatile("cp.async.cg.shared.global [%0], [%1], 16;" :: "r"(dst), "l"(src) : "memory")
#define CP_MBAR_ARRIVE(mb) \
    asm volatile("cp.async.mbarrier.arrive.noinc.shared.b64 [%0];" :: "r"(mb) : "memory")
#define MBAR_INIT(a, c) \
    asm volatile("mbarrier.init.shared.b64 [%0], %1;" :: "r"(a), "r"((uint32_t)(c)) : "memory")
#define MBAR_ARRIVE(a) \
    asm volatile("mbarrier.arrive.shared.b64 _, [%0];" :: "r"(a) : "memory")
#define MBAR_WAIT(addr, parity) do { \
    uint32_t _m = (addr), _p = (uint32_t)(parity), _d; \
    asm volatile("{ .reg .pred p; mbarrier.try_wait.parity.acquire.cta.shared::cta.b64 p, [%1], %2; selp.b32 %0,1,0,p; }" \
        : "=r"(_d) : "r"(_m), "r"(_p) : "memory"); \
    if (!_d) { \
        asm volatile("{ .reg .pred P1; WL_%=: mbarrier.try_wait.parity.acquire.cta.shared::cta.b64 P1, [%0], %1, 0x989680; @P1 bra.uni WD_%=; bra.uni WL_%=; WD_%=: }" \
            :: "r"(_m), "r"(_p) : "memory"); \
    } \
} while (0)

#define LDMX4(r0, r1, r2, r3, a) \
    asm volatile("ldmatrix.sync.aligned.m8n8.x4.shared.b16 {%0,%1,%2,%3}, [%4];" \
        : "=r"(r0), "=r"(r1), "=r"(r2), "=r"(r3) : "r"(a))
#define HMUL2(d, a, b) asm("mul.rn.f16x2 %0, %1, %2;" : "=r"(d) : "r"(a), "r"(b))

__device__ __forceinline__ void mma_f16_16816(float& c0, float& c1, float& c2, float& c3,
                                              uint32_t a0, uint32_t a1, uint32_t a2, uint32_t a3,
                                              uint32_t b0, uint32_t b1) {
    asm volatile(
        "mma.sync.aligned.m16n8k16.row.col.f32.f16.f16.f32 "
        "{%0,%1,%2,%3}, {%4,%5,%6,%7}, {%8,%9}, {%0,%1,%2,%3};"
        : "+f"(c0), "+f"(c1), "+f"(c2), "+f"(c3)
        : "r"(a0), "r"(a1), "r"(a2), "r"(a3), "r"(b0), "r"(b1));
}

// ---------------- prepass kernels ----------------
__global__ void __launch_bounds__(1024) transpose_x(const float* __restrict__ x) {
    __shared__ float t[32][33];
    const int bi = blockIdx.x * 32;
    const int bn = blockIdx.y * 32;
    t[threadIdx.y][threadIdx.x] = x[(size_t)(bn + threadIdx.y) * IDIM + bi + threadIdx.x];
    __syncthreads();
    g_xT[(size_t)(bi + threadIdx.y) * NROWS + bn + threadIdx.x] = t[threadIdx.x][threadIdx.y];
}

// W[d][i][o] fp32 -> g_Wt[i][o][d] fp16
__global__ void __launch_bounds__(1024) prep_w(const float* __restrict__ W) {
    __shared__ float sm[32][65];
    const int i  = blockIdx.x;
    const int ob = blockIdx.y * 32;
    const int tx = threadIdx.x, ty = threadIdx.y;
#pragma unroll
    for (int k = 0; k < 2; ++k) {
        int d = ty + k * 32;
        sm[tx][d] = W[(size_t)d * IDIM * ODIM + (size_t)i * ODIM + ob + tx];
    }
    __syncthreads();
    __half2 h = __floats2half2_rn(sm[ty][2 * tx], sm[ty][2 * tx + 1]);
    reinterpret_cast<__half2*>(g_Wt)[((size_t)i * ODIM + ob + ty) * 32 + tx] = h;
}

// b1[d][o] fp32 -> g_bt[o][d] fp16
__global__ void __launch_bounds__(1024) prep_b(const float* __restrict__ b1) {
    __shared__ float sm[32][65];
    const int ob = blockIdx.x * 32;
    const int tx = threadIdx.x, ty = threadIdx.y;
#pragma unroll
    for (int k = 0; k < 2; ++k) {
        int d = ty + k * 32;
        sm[tx][d] = b1[(size_t)d * ODIM + ob + tx];
    }
    __syncthreads();
    __half2 h = __floats2half2_rn(sm[ty][2 * tx], sm[ty][2 * tx + 1]);
    reinterpret_cast<__half2*>(g_bt)[(size_t)(ob + ty) * 32 + tx] = h;
}

// ---------------- main kernel: mbarrier pipeline, no CTA-wide sync in mainloop ----------------
__global__ void __launch_bounds__(NTH, 2) mlp_mma(
    const float* __restrict__ var,
    float* __restrict__ out)
{
    extern __shared__ __align__(128) uint8_t smem[];
    const uint32_t s0 = smem_u32(smem);
    const uint32_t fullB  = s0 + BAR_OFF;        // full[s]  @ +8s
    const uint32_t emptyB = s0 + BAR_OFF + 48u;  // empty[s] @ +8s

    const int tid  = threadIdx.x;
    const int lane = tid & 31;
    const int w    = tid >> 5;
    const int rowBase = blockIdx.y * BM;
    const int colBase = blockIdx.x * BN;

    const int wm = (w & 3) * 32;    // warp m-base (4 warps over M)
    const int wn = (w >> 2) * 32;   // warp n-base (2 warps over N)
    const int c  = lane & 3;
    const int g  = lane >> 2;

    if (tid == 0) {
#pragma unroll
        for (int s = 0; s < NSTAGE; ++s) {
            MBAR_INIT(fullB + 8u * s, NTH);
            MBAR_INIT(emptyB + 8u * s, NTH);
        }
    }

    // ----- this thread's 4 fragment rows -----
    int xr[4];
#pragma unroll
    for (int rr = 0; rr < 4; ++rr)
        xr[rr] = rowBase + wm + (rr >> 1) * 16 + (rr & 1) * 8 + g;

    // ----- v fragments in registers, loaded ONCE -----
    uint32_t vh[4][4][2];
#pragma unroll
    for (int rr = 0; rr < 4; ++rr) {
        const float* vp = var + (size_t)xr[rr] * DDIM;
#pragma unroll
        for (int grp = 0; grp < 4; ++grp) {
            float2 p0 = *reinterpret_cast<const float2*>(vp + grp * 16 + 2 * c);
            float2 p1 = *reinterpret_cast<const float2*>(vp + grp * 16 + 8 + 2 * c);
            vh[rr][grp][0] = pack2(p0.x, p0.y);
            vh[rr][grp][1] = pack2(p1.x, p1.y);
        }
    }

    // ----- ldmatrix per-lane base -----
    const int q = lane >> 3, r8 = lane & 7;
    const uint32_t bRowLd = (uint32_t)(wn + ((q >> 1) << 3) + r8) * BPITCHB
                          + (uint32_t)(q & 1) * 16u;

    // ----- B loader (cp.async) -----
    const int bo = tid >> 2;
    const int ci = tid & 3;
    auto issueB = [&](int t, int s) {
        const uint32_t dstBase = s0 + (uint32_t)s * B_STAGE + (uint32_t)bo * BPITCHB;
        if (t < NT_W) {
            const __half* p0 = g_Wt + ((size_t)(2 * t) * ODIM + colBase + bo) * DDIM;
            const __half* p1 = p0 + (size_t)ODIM * DDIM;
#pragma unroll
            for (int cc = 0; cc < 2; ++cc) {
                uint32_t ch = (uint32_t)(ci + cc * 4);
                CP_ASYNC16(dstBase + ch * 16u,        p0 + ch * 8);
                CP_ASYNC16(dstBase + 128u + ch * 16u, p1 + ch * 8);
            }
        } else {    // bias: k 0..63 only (upper half never read)
            const __half* p0 = g_bt + (size_t)(colBase + bo) * DDIM;
#pragma unroll
            for (int cc = 0; cc < 2; ++cc) {
                uint32_t ch = (uint32_t)(ci + cc * 4);
                CP_ASYNC16(dstBase + ch * 16u, p0 + ch * 8);
            }
        }
        CP_MBAR_ARRIVE(fullB + 8u * s);
    };
    auto loadXf = [&](int t, float (&dst)[2][4]) {
        if (t < NT_W) {
#pragma unroll
            for (int il = 0; il < 2; ++il)
#pragma unroll
                for (int rr = 0; rr < 4; ++rr)
                    dst[il][rr] = __ldg(&g_xT[(size_t)(2 * t + il) * NROWS + xr[rr]]);
        }
    };

    float C[2][4][4];
#pragma unroll
    for (int mt = 0; mt < 2; ++mt)
#pragma unroll
        for (int nt = 0; nt < 4; ++nt)
#pragma unroll
            for (int qq = 0; qq < 4; ++qq) C[mt][nt][qq] = 0.0f;

    __syncthreads();   // mbarrier init visible (only CTA-wide sync before epilogue)

    // ----- prologue: fill all 6 stages (fresh empty barriers: no wait needed) -----
#pragma unroll
    for (int t = 0; t < NSTAGE; ++t) issueB(t, t);

    float xf[2][4];
    loadXf(0, xf);

    // ----- mainloop: per-warp progress, no CTA-wide barriers -----
    int s = 0, w6 = 0;
    for (int t = 0; t <= NT_W; ++t) {
        const uint32_t par = (uint32_t)(w6 & 1);
        MBAR_WAIT(fullB + 8u * s, par);

        uint32_t xh[2][4];
#pragma unroll
        for (int il = 0; il < 2; ++il)
#pragma unroll
            for (int rr = 0; rr < 4; ++rr) xh[il][rr] = f2h2(xf[il][rr]);
        loadXf(t + 1, xf);

        const uint32_t base = s0 + (uint32_t)s * B_STAGE + bRowLd;

        if (t < NT_W) {
            // 8 k-steps, B double-buffered: kk -> grp=kk>>1, il=kk&1, ks=il*4+grp
            uint32_t bb[2][4][2];
            LDMX4(bb[0][0][0], bb[0][0][1], bb[0][1][0], bb[0][1][1], base);
            LDMX4(bb[0][2][0], bb[0][2][1], bb[0][3][0], bb[0][3][1], base + 16u * BPITCHB);
#pragma unroll
            for (int kk = 0; kk < 8; ++kk) {
                const int grp = kk >> 1, il = kk & 1;
                const int cur = kk & 1;
                if (kk < 7) {
                    const int nk = kk + 1;
                    const int nks = (nk & 1) * 4 + (nk >> 1);
                    const int nxt = cur ^ 1;
                    LDMX4(bb[nxt][0][0], bb[nxt][0][1], bb[nxt][1][0], bb[nxt][1][1],
                          base + (uint32_t)nks * 32u);
                    LDMX4(bb[nxt][2][0], bb[nxt][2][1], bb[nxt][3][0], bb[nxt][3][1],
                          base + (uint32_t)nks * 32u + 16u * BPITCHB);
                }
                uint32_t a[2][4];
#pragma unroll
                for (int mt = 0; mt < 2; ++mt) {
                    HMUL2(a[mt][0], xh[il][mt * 2 + 0], vh[mt * 2 + 0][grp][0]);
                    HMUL2(a[mt][1], xh[il][mt * 2 + 1], vh[mt * 2 + 1][grp][0]);
                    HMUL2(a[mt][2], xh[il][mt * 2 + 0], vh[mt * 2 + 0][grp][1]);
                    HMUL2(a[mt][3], xh[il][mt * 2 + 1], vh[mt * 2 + 1][grp][1]);
                }
#pragma unroll
                for (int mt = 0; mt < 2; ++mt)
#pragma unroll
                    for (int nt = 0; nt < 4; ++nt)
                        mma_f16_16816(C[mt][nt][0], C[mt][nt][1], C[mt][nt][2], C[mt][nt][3],
                                      a[mt][0], a[mt][1], a[mt][2], a[mt][3],
                                      bb[cur][nt][0], bb[cur][nt][1]);
            }
        } else {
            // bias tile: 4 real k-steps (ks 0..3), x = 1 -> a = v
#pragma unroll
            for (int ks = 0; ks < 4; ++ks) {
                uint32_t b[4][2];
                LDMX4(b[0][0], b[0][1], b[1][0], b[1][1], base + (uint32_t)ks * 32u);
                LDMX4(b[2][0], b[2][1], b[3][0], b[3][1],
                      base + (uint32_t)ks * 32u + 16u * BPITCHB);
                uint32_t a[2][4];
#pragma unroll
                for (int mt = 0; mt < 2; ++mt) {
                    a[mt][0] = vh[mt * 2 + 0][ks][0];
                    a[mt][1] = vh[mt * 2 + 1][ks][0];
                    a[mt][2] = vh[mt * 2 + 0][ks][1];
                    a[mt][3] = vh[mt * 2 + 1][ks][1];
                }
#pragma unroll
                for (int mt = 0; mt < 2; ++mt)
#pragma unroll
                    for (int nt = 0; nt < 4; ++nt)
                        mma_f16_16816(C[mt][nt][0], C[mt][nt][1], C[mt][nt][2], C[mt][nt][3],
                                      a[mt][0], a[mt][1], a[mt][2], a[mt][3],
                                      b[nt][0], b[nt][1]);
            }
        }

        MBAR_ARRIVE(emptyB + 8u * s);

        if (t + NSTAGE <= NT_W) {
            MBAR_WAIT(emptyB + 8u * s, par);   // all 256 threads done reading tile t
            issueB(t + NSTAGE, s);
        }

        if (++s == NSTAGE) { s = 0; ++w6; }
    }

    // ----- epilogue: per-warp, no sync needed -----
#pragma unroll
    for (int mt = 0; mt < 2; ++mt) {
        const int r0 = rowBase + wm + mt * 16 + g;
#pragma unroll
        for (int nt = 0; nt < 4; ++nt) {
            const int c0i = colBase + wn + nt * 8 + c * 2;
            float2 v0, v1;
            v0.x = C[mt][nt][0]; v0.y = C[mt][nt][1];
            v1.x = C[mt][nt][2]; v1.y = C[mt][nt][3];
            *reinterpret_cast<float2*>(&out[(size_t)r0 * ODIM + c0i]) = v0;
            *reinterpret_cast<float2*>(&out[(size_t)(r0 + 8) * ODIM + c0i]) = v1;
        }
    }
}

// ---------------- host ----------------
extern "C" void kernel_launch(void* const* d_in, const int* in_sizes, int n_in,
                              void* d_out, int out_size) {
    const float* x   = (const float*)d_in[0];   // [4096, 512]
    const float* var = (const float*)d_in[1];   // [4096, 64]
    const float* W   = (const float*)d_in[2];   // [64, 512, 512]
    const float* b1  = (const float*)d_in[3];   // [64, 512]
    float* out       = (float*)d_out;           // [4096, 512]

    {
        dim3 tb(32, 32), tg(IDIM / 32, NROWS / 32);
        transpose_x<<<tg, tb>>>(x);
    }
    {
        dim3 tb(32, 32), tg(IDIM, ODIM / 32);
        prep_w<<<tg, tb>>>(W);
    }
    {
        dim3 tb(32, 32);
        prep_b<<<ODIM / 32, tb>>>(b1);
    }

    cudaFuncSetAttribute(mlp_mma, cudaFuncAttributeMaxDynamicSharedMemorySize, SMEM_TOTAL);
    dim3 grid(ODIM / BN, NROWS / BM);   // (8, 32) = 256 CTAs, 2 per SM
    mlp_mma<<<grid, NTH, SMEM_TOTAL>>>(var, out);
}